// round 3
// baseline (speedup 1.0000x reference)
#include <cuda_runtime.h>
#include <math.h>

// Problem constants (fixed by the dataset)
#define N_NODES 80000
#define N_EDGES 1280000
#define FDIM    64

// -------- scratch: static __device__ arrays, 16B-aligned for vector access --
__device__ __align__(16) float g_Y[N_NODES * FDIM];   // GEMM out, scaled by dinv
__device__ __align__(16) float g_A[N_NODES * FDIM];   // hidden activations
__device__ __align__(16) float g_dinv[N_NODES];       // 1/sqrt(1 + indeg)
__device__ __align__(16) int   g_cnt[N_NODES];        // in-degree histogram
__device__ __align__(16) int   g_cur[N_NODES];        // CSR fill cursors
__device__ __align__(16) int   g_rowptr[N_NODES + 1]; // CSR row pointers (dst)
__device__ __align__(16) int   g_col[N_EDGES];        // CSR: src per in-edge
__device__            int   g_is64;                   // 1 if edges stored int64

// ---------------------------------------------------------------------------
// Detect edge_index storage width. For little-endian int64 with values
// < 2^31, every odd int32 word is 0. For int32 data (values uniform in
// [0, 80000)), 64 consecutive zeros at odd positions is impossible.
__global__ void k_detect(const int* __restrict__ EI, int* __restrict__ flag) {
    int t = threadIdx.x;                    // 0..63
    int v = EI[2 * t + 1];
    unsigned any = __ballot_sync(0xffffffffu, v != 0);
    __shared__ int nz[2];
    if ((t & 31) == 0) nz[t >> 5] = (any != 0);
    __syncthreads();
    if (t == 0) *flag = (nz[0] == 0 && nz[1] == 0) ? 1 : 0;
}

__device__ __forceinline__ int edge_src(const int* EI, int e, int is64) {
    return is64 ? EI[2 * e] : EI[e];
}
__device__ __forceinline__ int edge_dst(const int* EI, int e, int is64) {
    return is64 ? EI[2 * (N_EDGES + e)] : EI[N_EDGES + e];
}

// ---------------------------------------------------------------------------
__global__ void k_zero(int* __restrict__ cnt, int* __restrict__ cur) {
    int i = blockIdx.x * blockDim.x + threadIdx.x;
    if (i < N_NODES) { cnt[i] = 0; cur[i] = 0; }
}

__global__ void k_hist(const int* __restrict__ EI, int* __restrict__ cnt,
                       const int* __restrict__ flag) {
    int e = blockIdx.x * blockDim.x + threadIdx.x;
    if (e < N_EDGES) {
        int d = edge_dst(EI, e, *flag);
        atomicAdd(&cnt[d], 1);
    }
}

// Single-block exclusive scan of cnt -> rowptr (80000 elements, 1024 threads)
__global__ void k_scan(const int* __restrict__ cnt, int* __restrict__ rowptr) {
    __shared__ int s[1024];
    const int t = threadIdx.x;
    const int CH = (N_NODES + 1023) / 1024;   // 79 per thread
    int b0 = t * CH;
    int b1 = min(b0 + CH, N_NODES);
    int sum = 0;
    for (int i = b0; i < b1; i++) sum += cnt[i];
    s[t] = sum;
    __syncthreads();
    for (int off = 1; off < 1024; off <<= 1) {
        int v = (t >= off) ? s[t - off] : 0;
        __syncthreads();
        s[t] += v;
        __syncthreads();
    }
    int run = s[t] - sum;   // exclusive base for this thread's chunk
    for (int i = b0; i < b1; i++) {
        rowptr[i] = run;
        run += cnt[i];
    }
    if (t == 1023) rowptr[N_NODES] = s[1023];
}

__global__ void k_dinv(const int* __restrict__ cnt, float* __restrict__ dinv) {
    int i = blockIdx.x * blockDim.x + threadIdx.x;
    if (i < N_NODES) dinv[i] = rsqrtf(1.0f + (float)cnt[i]);
}

__global__ void k_fill(const int* __restrict__ EI,
                       const int* __restrict__ rowptr,
                       int* __restrict__ cur,
                       int* __restrict__ col,
                       const int* __restrict__ flag) {
    int e = blockIdx.x * blockDim.x + threadIdx.x;
    if (e < N_EDGES) {
        int is64 = *flag;
        int s = edge_src(EI, e, is64);
        int d = edge_dst(EI, e, is64);
        int p = rowptr[d] + atomicAdd(&cur[d], 1);
        col[p] = s;
    }
}

// ---------------------------------------------------------------------------
// GEMM: Y[r] = (in[r] @ W) * dinv[r]   (64x64 W; 64-row tiles; 16x16 threads)
__global__ __launch_bounds__(256) void k_gemm(const float* __restrict__ in,
                                              const float* __restrict__ W,
                                              const float* __restrict__ dinv,
                                              float* __restrict__ Y) {
    __shared__ __align__(16) float Ws[64][64];
    __shared__ __align__(16) float Xs[64][64];

    const int tx = threadIdx.x;      // 0..15
    const int ty = threadIdx.y;      // 0..15
    const int tid = ty * 16 + tx;    // 0..255
    const int row0 = blockIdx.x * 64;

    const float4* Wg = (const float4*)W;
    const float4* Xg = (const float4*)(in + (size_t)row0 * FDIM);
    float4* Wsh = (float4*)Ws;
    float4* Xsh = (float4*)Xs;
    #pragma unroll
    for (int i = 0; i < 4; i++) {
        Wsh[tid + i * 256] = Wg[tid + i * 256];
        Xsh[tid + i * 256] = Xg[tid + i * 256];
    }
    __syncthreads();

    float acc[4][4] = {};
    #pragma unroll 16
    for (int k = 0; k < 64; k++) {
        float4 b = *(const float4*)&Ws[k][tx * 4];
        #pragma unroll
        for (int i = 0; i < 4; i++) {
            float a = Xs[ty * 4 + i][k];
            acc[i][0] += a * b.x;
            acc[i][1] += a * b.y;
            acc[i][2] += a * b.z;
            acc[i][3] += a * b.w;
        }
    }

    #pragma unroll
    for (int i = 0; i < 4; i++) {
        int r = row0 + ty * 4 + i;
        float dv = dinv[r];
        float4 o;
        o.x = acc[i][0] * dv;
        o.y = acc[i][1] * dv;
        o.z = acc[i][2] * dv;
        o.w = acc[i][3] * dv;
        *(float4*)&Y[(size_t)r * FDIM + tx * 4] = o;
    }
}

// ---------------------------------------------------------------------------
// Aggregation: one warp per node.
//   out[i] = maybe_relu( dinv[i] * ( Y[i] + sum_{src in CSR[i]} Y[src] ) + b )
__global__ __launch_bounds__(256) void k_agg(const float* __restrict__ Y,
                                             const int* __restrict__ rowptr,
                                             const int* __restrict__ col,
                                             const float* __restrict__ dinv,
                                             const float* __restrict__ bias,
                                             float* __restrict__ out,
                                             int do_relu) {
    int gw = (blockIdx.x * blockDim.x + threadIdx.x) >> 5;   // warp = node
    int lane = threadIdx.x & 31;
    if (gw >= N_NODES) return;

    const float2* Y2 = (const float2*)Y;
    float2 acc = Y2[(size_t)gw * 32 + lane];   // self-loop term (already *dinv)

    int beg = rowptr[gw];
    int end = rowptr[gw + 1];
    for (int j = beg; j < end; j += 32) {
        int idx = j + lane;
        int id = (idx < end) ? col[idx] : 0;
        int cnt = min(32, end - j);
        for (int t = 0; t < cnt; t++) {
            int src = __shfl_sync(0xffffffffu, id, t);
            float2 v = Y2[(size_t)src * 32 + lane];
            acc.x += v.x;
            acc.y += v.y;
        }
    }

    float dv = dinv[gw];
    float2 bv = ((const float2*)bias)[lane];
    float2 r;
    r.x = acc.x * dv + bv.x;
    r.y = acc.y * dv + bv.y;
    if (do_relu) {
        r.x = fmaxf(r.x, 0.0f);
        r.y = fmaxf(r.y, 0.0f);
    }
    ((float2*)out)[(size_t)gw * 32 + lane] = r;
}

// ---------------------------------------------------------------------------
extern "C" void kernel_launch(void* const* d_in, const int* in_sizes, int n_in,
                              void* d_out, int out_size) {
    const float* X  = (const float*)d_in[0];
    const int*   EI = (const int*)d_in[1];   // edge_index (int32; int64 auto-detected)
    const float* W1 = (const float*)d_in[2];
    const float* b1 = (const float*)d_in[3];
    const float* W2 = (const float*)d_in[4];
    const float* b2 = (const float*)d_in[5];
    const float* W3 = (const float*)d_in[6];
    const float* b3 = (const float*)d_in[7];
    float* out = (float*)d_out;

    void *pY, *pA, *pDinv, *pCnt, *pCur, *pRow, *pCol, *pFlag;
    cudaGetSymbolAddress(&pY, g_Y);
    cudaGetSymbolAddress(&pA, g_A);
    cudaGetSymbolAddress(&pDinv, g_dinv);
    cudaGetSymbolAddress(&pCnt, g_cnt);
    cudaGetSymbolAddress(&pCur, g_cur);
    cudaGetSymbolAddress(&pRow, g_rowptr);
    cudaGetSymbolAddress(&pCol, g_col);
    cudaGetSymbolAddress(&pFlag, g_is64);
    float* Yb   = (float*)pY;
    float* Ab   = (float*)pA;
    float* dinv = (float*)pDinv;
    int*   cnt  = (int*)pCnt;
    int*   cur  = (int*)pCur;
    int*   row  = (int*)pRow;
    int*   colA = (int*)pCol;
    int*   flag = (int*)pFlag;

    const int nodeBlocks = (N_NODES + 255) / 256;
    const int edgeBlocks = (N_EDGES + 255) / 256;
    const int gemmBlocks = N_NODES / 64;                  // 1250
    const int aggBlocks  = (N_NODES * 32 + 255) / 256;    // 10000 (warp/node)

    // --- graph structure build ---
    k_detect<<<1, 64>>>(EI, flag);
    k_zero<<<nodeBlocks, 256>>>(cnt, cur);
    k_hist<<<edgeBlocks, 256>>>(EI, cnt, flag);
    k_scan<<<1, 1024>>>(cnt, row);
    k_dinv<<<nodeBlocks, 256>>>(cnt, dinv);
    k_fill<<<edgeBlocks, 256>>>(EI, row, cur, colA, flag);

    dim3 gThr(16, 16);

    // --- layer 1: X -> g_A ---
    k_gemm<<<gemmBlocks, gThr>>>(X, W1, dinv, Yb);
    k_agg<<<aggBlocks, 256>>>(Yb, row, colA, dinv, b1, Ab, 1);

    // --- layer 2: g_A -> g_A ---
    k_gemm<<<gemmBlocks, gThr>>>(Ab, W2, dinv, Yb);
    k_agg<<<aggBlocks, 256>>>(Yb, row, colA, dinv, b2, Ab, 1);

    // --- layer 3: g_A -> d_out (no relu) ---
    k_gemm<<<gemmBlocks, gThr>>>(Ab, W3, dinv, Yb);
    k_agg<<<aggBlocks, 256>>>(Yb, row, colA, dinv, b3, out, 0);
}

// round 4
// speedup vs baseline: 1.3029x; 1.3029x over previous
#include <cuda_runtime.h>
#include <math.h>

// Problem constants (fixed by the dataset)
#define N_NODES 80000
#define N_EDGES 1280000
#define FDIM    64
#define SCAN_BLOCKS 313           // ceil(80000 / 256)

// -------- scratch: static __device__ arrays, 16B-aligned for vector access --
__device__ __align__(16) float g_Y[N_NODES * FDIM];   // GEMM out, scaled by dinv
__device__ __align__(16) float g_A[N_NODES * FDIM];   // hidden activations
__device__ __align__(16) float g_dinv[N_NODES];       // 1/sqrt(1 + indeg)
__device__ __align__(16) int   g_cnt[N_NODES];        // in-degree histogram
__device__ __align__(16) int   g_cur[N_NODES];        // CSR fill cursors
__device__ __align__(16) int   g_rowptr[N_NODES + 1]; // CSR row pointers (dst)
__device__ __align__(16) int   g_col[N_EDGES];        // CSR: src per in-edge
__device__ __align__(16) int   g_bsum[SCAN_BLOCKS];   // scan block partials
__device__ __align__(16) int   g_bbase[SCAN_BLOCKS];  // scan block offsets
__device__            int   g_is64;                   // 1 if edges stored int64

// ---------------------------------------------------------------------------
// Detect edge_index storage width. For little-endian int64 with values
// < 2^31, every odd int32 word is 0. For int32 data (values uniform in
// [0, 80000)), 64 consecutive zeros at odd positions is impossible.
__global__ void k_detect(const int* __restrict__ EI, int* __restrict__ flag) {
    int t = threadIdx.x;                    // 0..63
    int v = EI[2 * t + 1];
    unsigned any = __ballot_sync(0xffffffffu, v != 0);
    __shared__ int nz[2];
    if ((t & 31) == 0) nz[t >> 5] = (any != 0);
    __syncthreads();
    if (t == 0) *flag = (nz[0] == 0 && nz[1] == 0) ? 1 : 0;
}

__device__ __forceinline__ int edge_src(const int* EI, int e, int is64) {
    return is64 ? EI[2 * e] : EI[e];
}
__device__ __forceinline__ int edge_dst(const int* EI, int e, int is64) {
    return is64 ? EI[2 * (N_EDGES + e)] : EI[N_EDGES + e];
}

// ---------------------------------------------------------------------------
__global__ void k_zero(int* __restrict__ cnt, int* __restrict__ cur) {
    int i = blockIdx.x * blockDim.x + threadIdx.x;
    if (i < N_NODES) { cnt[i] = 0; cur[i] = 0; }
}

__global__ void k_hist(const int* __restrict__ EI, int* __restrict__ cnt,
                       const int* __restrict__ flag) {
    int e = blockIdx.x * blockDim.x + threadIdx.x;
    if (e < N_EDGES) {
        int d = edge_dst(EI, e, *flag);
        atomicAdd(&cnt[d], 1);
    }
}

// --- 3-phase multi-block exclusive scan of cnt -> rowptr ------------------
// Phase 1: per-block (256 elems) sums.
__global__ __launch_bounds__(256) void k_scan1(const int* __restrict__ cnt,
                                               int* __restrict__ bsum) {
    int i = blockIdx.x * 256 + threadIdx.x;
    int v = (i < N_NODES) ? cnt[i] : 0;
    // warp reduce then shared combine
    #pragma unroll
    for (int off = 16; off > 0; off >>= 1)
        v += __shfl_down_sync(0xffffffffu, v, off);
    __shared__ int w[8];
    if ((threadIdx.x & 31) == 0) w[threadIdx.x >> 5] = v;
    __syncthreads();
    if (threadIdx.x < 8) {
        int s = w[threadIdx.x];
        #pragma unroll
        for (int off = 4; off > 0; off >>= 1)
            s += __shfl_down_sync(0xffu, s, off);
        if (threadIdx.x == 0) bsum[blockIdx.x] = s;
    }
}

// Phase 2: single small block scans the 313 partials -> exclusive bases.
__global__ __launch_bounds__(512) void k_scan2(const int* __restrict__ bsum,
                                               int* __restrict__ bbase,
                                               int* __restrict__ rowptr) {
    __shared__ int s[512];
    int t = threadIdx.x;
    int v = (t < SCAN_BLOCKS) ? bsum[t] : 0;
    s[t] = v;
    __syncthreads();
    #pragma unroll
    for (int off = 1; off < 512; off <<= 1) {
        int u = (t >= off) ? s[t - off] : 0;
        __syncthreads();
        s[t] += u;
        __syncthreads();
    }
    if (t < SCAN_BLOCKS) bbase[t] = s[t] - v;   // exclusive
    if (t == 0) rowptr[N_NODES] = N_EDGES;      // total is known a priori
}

// Phase 3: per-block exclusive scan + base; also emit dinv (cnt in hand).
__global__ __launch_bounds__(256) void k_scan3(const int* __restrict__ cnt,
                                               const int* __restrict__ bbase,
                                               int* __restrict__ rowptr,
                                               float* __restrict__ dinv) {
    __shared__ int s[256];
    int t = threadIdx.x;
    int i = blockIdx.x * 256 + t;
    int v = (i < N_NODES) ? cnt[i] : 0;
    s[t] = v;
    __syncthreads();
    #pragma unroll
    for (int off = 1; off < 256; off <<= 1) {
        int u = (t >= off) ? s[t - off] : 0;
        __syncthreads();
        s[t] += u;
        __syncthreads();
    }
    if (i < N_NODES) {
        rowptr[i] = bbase[blockIdx.x] + s[t] - v;   // exclusive
        dinv[i] = rsqrtf(1.0f + (float)v);
    }
}

__global__ void k_fill(const int* __restrict__ EI,
                       const int* __restrict__ rowptr,
                       int* __restrict__ cur,
                       int* __restrict__ col,
                       const int* __restrict__ flag) {
    int e = blockIdx.x * blockDim.x + threadIdx.x;
    if (e < N_EDGES) {
        int is64 = *flag;
        int s = edge_src(EI, e, is64);
        int d = edge_dst(EI, e, is64);
        int p = rowptr[d] + atomicAdd(&cur[d], 1);
        col[p] = s;
    }
}

// ---------------------------------------------------------------------------
// GEMM: Y[r] = (in[r] @ W) * dinv[r]   (64x64 W; 64-row tiles; 16x16 threads)
__global__ __launch_bounds__(256) void k_gemm(const float* __restrict__ in,
                                              const float* __restrict__ W,
                                              const float* __restrict__ dinv,
                                              float* __restrict__ Y) {
    __shared__ __align__(16) float Ws[64][64];
    __shared__ __align__(16) float Xs[64][64];

    const int tx = threadIdx.x;      // 0..15
    const int ty = threadIdx.y;      // 0..15
    const int tid = ty * 16 + tx;    // 0..255
    const int row0 = blockIdx.x * 64;

    const float4* Wg = (const float4*)W;
    const float4* Xg = (const float4*)(in + (size_t)row0 * FDIM);
    float4* Wsh = (float4*)Ws;
    float4* Xsh = (float4*)Xs;
    #pragma unroll
    for (int i = 0; i < 4; i++) {
        Wsh[tid + i * 256] = Wg[tid + i * 256];
        Xsh[tid + i * 256] = Xg[tid + i * 256];
    }
    __syncthreads();

    float acc[4][4] = {};
    #pragma unroll 16
    for (int k = 0; k < 64; k++) {
        float4 b = *(const float4*)&Ws[k][tx * 4];
        #pragma unroll
        for (int i = 0; i < 4; i++) {
            float a = Xs[ty * 4 + i][k];
            acc[i][0] += a * b.x;
            acc[i][1] += a * b.y;
            acc[i][2] += a * b.z;
            acc[i][3] += a * b.w;
        }
    }

    #pragma unroll
    for (int i = 0; i < 4; i++) {
        int r = row0 + ty * 4 + i;
        float dv = dinv[r];
        float4 o;
        o.x = acc[i][0] * dv;
        o.y = acc[i][1] * dv;
        o.z = acc[i][2] * dv;
        o.w = acc[i][3] * dv;
        *(float4*)&Y[(size_t)r * FDIM + tx * 4] = o;
    }
}

// ---------------------------------------------------------------------------
// Aggregation: one warp per node; 4 independent accumulators for MLP.
//   out[i] = maybe_relu( dinv[i] * ( Y[i] + sum_{src in CSR[i]} Y[src] ) + b )
__global__ __launch_bounds__(256) void k_agg(const float* __restrict__ Y,
                                             const int* __restrict__ rowptr,
                                             const int* __restrict__ col,
                                             const float* __restrict__ dinv,
                                             const float* __restrict__ bias,
                                             float* __restrict__ out,
                                             int do_relu) {
    int gw = (blockIdx.x * blockDim.x + threadIdx.x) >> 5;   // warp = node
    int lane = threadIdx.x & 31;
    if (gw >= N_NODES) return;

    const float2* Y2 = (const float2*)Y;
    float2 a0 = Y2[(size_t)gw * 32 + lane];   // self-loop term (already *dinv)
    float2 a1 = {0.f, 0.f}, a2 = {0.f, 0.f}, a3 = {0.f, 0.f};

    int beg = rowptr[gw];
    int end = rowptr[gw + 1];
    for (int j = beg; j < end; j += 32) {
        int idx = j + lane;
        int id = (idx < end) ? col[idx] : 0;
        int cnt = min(32, end - j);
        int t = 0;
        for (; t + 4 <= cnt; t += 4) {
            int s0 = __shfl_sync(0xffffffffu, id, t);
            int s1 = __shfl_sync(0xffffffffu, id, t + 1);
            int s2 = __shfl_sync(0xffffffffu, id, t + 2);
            int s3 = __shfl_sync(0xffffffffu, id, t + 3);
            float2 v0 = Y2[(size_t)s0 * 32 + lane];
            float2 v1 = Y2[(size_t)s1 * 32 + lane];
            float2 v2 = Y2[(size_t)s2 * 32 + lane];
            float2 v3 = Y2[(size_t)s3 * 32 + lane];
            a0.x += v0.x; a0.y += v0.y;
            a1.x += v1.x; a1.y += v1.y;
            a2.x += v2.x; a2.y += v2.y;
            a3.x += v3.x; a3.y += v3.y;
        }
        for (; t < cnt; t++) {
            int s0 = __shfl_sync(0xffffffffu, id, t);
            float2 v0 = Y2[(size_t)s0 * 32 + lane];
            a0.x += v0.x; a0.y += v0.y;
        }
    }

    float2 acc;
    acc.x = (a0.x + a1.x) + (a2.x + a3.x);
    acc.y = (a0.y + a1.y) + (a2.y + a3.y);

    float dv = dinv[gw];
    float2 bv = ((const float2*)bias)[lane];
    float2 r;
    r.x = acc.x * dv + bv.x;
    r.y = acc.y * dv + bv.y;
    if (do_relu) {
        r.x = fmaxf(r.x, 0.0f);
        r.y = fmaxf(r.y, 0.0f);
    }
    ((float2*)out)[(size_t)gw * 32 + lane] = r;
}

// ---------------------------------------------------------------------------
extern "C" void kernel_launch(void* const* d_in, const int* in_sizes, int n_in,
                              void* d_out, int out_size) {
    const float* X  = (const float*)d_in[0];
    const int*   EI = (const int*)d_in[1];   // edge_index (int32; int64 auto-detected)
    const float* W1 = (const float*)d_in[2];
    const float* b1 = (const float*)d_in[3];
    const float* W2 = (const float*)d_in[4];
    const float* b2 = (const float*)d_in[5];
    const float* W3 = (const float*)d_in[6];
    const float* b3 = (const float*)d_in[7];
    float* out = (float*)d_out;

    void *pY, *pA, *pDinv, *pCnt, *pCur, *pRow, *pCol, *pFlag, *pBs, *pBb;
    cudaGetSymbolAddress(&pY, g_Y);
    cudaGetSymbolAddress(&pA, g_A);
    cudaGetSymbolAddress(&pDinv, g_dinv);
    cudaGetSymbolAddress(&pCnt, g_cnt);
    cudaGetSymbolAddress(&pCur, g_cur);
    cudaGetSymbolAddress(&pRow, g_rowptr);
    cudaGetSymbolAddress(&pCol, g_col);
    cudaGetSymbolAddress(&pFlag, g_is64);
    cudaGetSymbolAddress(&pBs, g_bsum);
    cudaGetSymbolAddress(&pBb, g_bbase);
    float* Yb   = (float*)pY;
    float* Ab   = (float*)pA;
    float* dinv = (float*)pDinv;
    int*   cnt  = (int*)pCnt;
    int*   cur  = (int*)pCur;
    int*   row  = (int*)pRow;
    int*   colA = (int*)pCol;
    int*   flag = (int*)pFlag;
    int*   bsum = (int*)pBs;
    int*   bbase= (int*)pBb;

    const int nodeBlocks = (N_NODES + 255) / 256;         // 313
    const int edgeBlocks = (N_EDGES + 255) / 256;
    const int gemmBlocks = N_NODES / 64;                  // 1250
    const int aggBlocks  = (N_NODES * 32 + 255) / 256;    // 10000 (warp/node)

    // --- graph structure build ---
    k_detect<<<1, 64>>>(EI, flag);
    k_zero<<<nodeBlocks, 256>>>(cnt, cur);
    k_hist<<<edgeBlocks, 256>>>(EI, cnt, flag);
    k_scan1<<<SCAN_BLOCKS, 256>>>(cnt, bsum);
    k_scan2<<<1, 512>>>(bsum, bbase, row);
    k_scan3<<<SCAN_BLOCKS, 256>>>(cnt, bbase, row, dinv);
    k_fill<<<edgeBlocks, 256>>>(EI, row, cur, colA, flag);

    dim3 gThr(16, 16);

    // --- layer 1: X -> g_A ---
    k_gemm<<<gemmBlocks, gThr>>>(X, W1, dinv, Yb);
    k_agg<<<aggBlocks, 256>>>(Yb, row, colA, dinv, b1, Ab, 1);

    // --- layer 2: g_A -> g_A ---
    k_gemm<<<gemmBlocks, gThr>>>(Ab, W2, dinv, Yb);
    k_agg<<<aggBlocks, 256>>>(Yb, row, colA, dinv, b2, Ab, 1);

    // --- layer 3: g_A -> d_out (no relu) ---
    k_gemm<<<gemmBlocks, gThr>>>(Ab, W3, dinv, Yb);
    k_agg<<<aggBlocks, 256>>>(Yb, row, colA, dinv, b3, out, 0);
}